// round 16
// baseline (speedup 1.0000x reference)
#include <cuda_runtime.h>
#include <cuda_fp16.h>
#include <cstdint>
#include <math.h>

#define BB 8
#define NN 1024
#define CC 768
#define HH 12
#define ZZ 64
#define BH (BB*HH)
#define SCALE 0.125f
typedef __half h16;

// ---------------- scratch ----------------
__device__ h16 g_xh[BB*NN*CC];
__device__ h16 g_Wqh[CC*CC], g_Wkh[CC*CC], g_Wph[CC*CC];
__device__ h16 g_U1h[CC*CC], g_U2h[CC*CC];
__device__ h16 g_Qh[BH*NN*ZZ], g_Kh[BH*NN*ZZ];
__device__ float g_m[BH*NN], g_il[BH*NN];
__device__ h16 g_Ckh[BB*NN*CC], g_Cqh[BB*NN*CC];

// ---------------- helpers ----------------
#define SW(o) ((o) ^ (((o)>>3)&0x70))
#define P1_A 0
#define P1_B 16384
#define STGP 32768
#define SMEMP 65536

__device__ __forceinline__ uint32_t smem_u32(const void* p){
    uint32_t a;
    asm("{ .reg .u64 t; cvta.to.shared.u64 t, %1; cvt.u32.u64 %0, t; }" : "=r"(a) : "l"(p));
    return a;
}
__device__ __forceinline__ void ldsm_x4(uint32_t& r0, uint32_t& r1, uint32_t& r2, uint32_t& r3, uint32_t addr){
    asm volatile("ldmatrix.sync.aligned.m8n8.x4.shared.b16 {%0,%1,%2,%3}, [%4];"
        : "=r"(r0), "=r"(r1), "=r"(r2), "=r"(r3) : "r"(addr));
}
__device__ __forceinline__ void ldsm_x4_t(uint32_t& r0, uint32_t& r1, uint32_t& r2, uint32_t& r3, uint32_t addr){
    asm volatile("ldmatrix.sync.aligned.m8n8.x4.trans.shared.b16 {%0,%1,%2,%3}, [%4];"
        : "=r"(r0), "=r"(r1), "=r"(r2), "=r"(r3) : "r"(addr));
}
__device__ __forceinline__ void mma16816(float c[4], const uint32_t a[4], uint32_t b0, uint32_t b1){
    asm volatile("mma.sync.aligned.m16n8k16.row.col.f32.f16.f16.f32 "
        "{%0,%1,%2,%3}, {%4,%5,%6,%7}, {%8,%9}, {%0,%1,%2,%3};"
        : "+f"(c[0]), "+f"(c[1]), "+f"(c[2]), "+f"(c[3])
        : "r"(a[0]), "r"(a[1]), "r"(a[2]), "r"(a[3]), "r"(b0), "r"(b1));
}
__device__ __forceinline__ void cp16(uint32_t saddr, const void* g){
    asm volatile("cp.async.cg.shared.global [%0], [%1], 16;" :: "r"(saddr), "l"(g));
}
#define CP_COMMIT() asm volatile("cp.async.commit_group;" ::: "memory")
#define CP_WAIT0()  asm volatile("cp.async.wait_group 0;" ::: "memory")

__device__ __forceinline__ float fexp(float x){
    float y = x * 1.4426950408889634f;
    float n = rintf(y);
    float f = y - n;
    float p = 1.3333558146428443e-3f;
    p = fmaf(p, f, 9.6181291076284772e-3f);
    p = fmaf(p, f, 5.5504108664821580e-2f);
    p = fmaf(p, f, 2.4022650695910072e-1f);
    p = fmaf(p, f, 6.9314718055994531e-1f);
    p = fmaf(p, f, 1.0f);
    return __int_as_float(__float_as_int(p) + (((int)n) << 23));
}
__device__ __forceinline__ uint32_t pack2h(float a, float b){
    return (uint32_t)__half_as_ushort(__float2half(a))
         | ((uint32_t)__half_as_ushort(__float2half(b)) << 16);
}

// async tile loader: rows x 64 h16 (128B rows), swizzled; nthr cooperating threads
__device__ __forceinline__ void ld_tile_a(uint32_t sbase, int off, const h16* __restrict__ g,
                                          int rows, int rstride, int tid, int nthr){
    for (int i = tid; i < rows*8; i += nthr){
        int r = i >> 3, c = i & 7;
        cp16(sbase + off + SW(r*128 + c*16), g + (size_t)r*rstride + c*8);
    }
}

// 16-warp 1-term block MMA: block 128x128, warp 32x32 (4x4 warp grid)
__device__ __forceinline__ void mma_w16(float c[2][4][4],
        uint32_t aH, uint32_t bH, int wm0, int wn0, int lane){
    const int lr = lane & 15, lh = lane >> 4;
#pragma unroll
    for (int ks = 0; ks < 4; ks++){
        uint32_t ah[2][4];
#pragma unroll
        for (int ma = 0; ma < 2; ma++){
            uint32_t off = SW((wm0 + ma*16 + lr)*128 + (ks*2 + lh)*16);
            ldsm_x4(ah[ma][0], ah[ma][1], ah[ma][2], ah[ma][3], aH + off);
        }
        uint32_t bh[2][4];
#pragma unroll
        for (int np = 0; np < 2; np++){
            uint32_t off = SW((wn0 + np*16 + lr)*128 + (ks*2 + lh)*16);
            ldsm_x4(bh[np][0], bh[np][1], bh[np][2], bh[np][3], bH + off);
        }
#pragma unroll
        for (int np = 0; np < 2; np++)
#pragma unroll
        for (int ma = 0; ma < 2; ma++){
            mma16816(c[ma][np*2],   ah[ma], bh[np][0], bh[np][2]);
            mma16816(c[ma][np*2+1], ah[ma], bh[np][1], bh[np][3]);
        }
    }
}

#define MMA_PRE16() \
    extern __shared__ char sm[]; \
    const int tid = threadIdx.x, wid = tid >> 5, lane = tid & 31; \
    const uint32_t sbase = smem_u32(sm); \
    const int wm0 = (wid & 3) * 32, wn0 = (wid >> 2) * 32; \
    float c[2][4][4]; \
    _Pragma("unroll") for (int i = 0; i < 2; i++) \
    _Pragma("unroll") for (int j = 0; j < 4; j++) \
    _Pragma("unroll") for (int k = 0; k < 4; k++) c[i][j][k] = 0.0f;

// ============================ fused converter ===============================
#define X4 (BB*NN*CC/4)
#define W4 (CC*CC/4)
__global__ __launch_bounds__(256) void k_conv_all(
    const float* __restrict__ x,  const float* __restrict__ Wq,
    const float* __restrict__ Wk, const float* __restrict__ Wp)
{
    const int total = X4 + 3*W4;
    for (int i = blockIdx.x*blockDim.x + threadIdx.x; i < total; i += gridDim.x*blockDim.x){
        const float* src; h16* dst; int off;
        if (i < X4)            { src = x;  dst = g_xh;  off = i; }
        else if (i < X4+W4)    { src = Wq; dst = g_Wqh; off = i - X4; }
        else if (i < X4+2*W4)  { src = Wk; dst = g_Wkh; off = i - X4 - W4; }
        else                   { src = Wp; dst = g_Wph; off = i - X4 - 2*W4; }
        float4 v = reinterpret_cast<const float4*>(src)[off];
        reinterpret_cast<uint2*>(dst)[off] = make_uint2(pack2h(v.x, v.y), pack2h(v.z, v.w));
    }
}

// ========= fused proj + weight GEMM (1-term, 512 thr, 16 warps) =============
__global__ __launch_bounds__(512) void k_gemm_fused(){
    const int zid = blockIdx.z;
    const bool isw = (zid == 2);
    if (isw && blockIdx.x >= 12) return;
    MMA_PRE16();
    const int n0 = blockIdx.y*128;
    int m0, sel = 0;
    const h16 *A, *B;
    if (!isw){
        m0 = blockIdx.x*128;
        A = g_xh + (size_t)m0*CC;
        B = (zid ? g_Wkh : g_Wqh) + (size_t)n0*CC;
    } else {
        sel = blockIdx.x >= 6;
        m0 = (blockIdx.x - (sel ? 6 : 0))*128;
        A = g_Wph + (size_t)m0*CC;
        B = (sel ? g_Wkh : g_Wqh) + (size_t)n0*CC;
    }
    ld_tile_a(sbase, P1_A, A, 128, CC, tid, 512);
    ld_tile_a(sbase, P1_B, B, 128, CC, tid, 512);
    CP_COMMIT();
    for (int kc = 0; kc < 12; kc++){
        CP_WAIT0();
        __syncthreads();
        if (kc + 1 < 12){
            int s2 = ((kc+1) & 1) * STGP;
            ld_tile_a(sbase, s2 + P1_A, A + (kc+1)*64, 128, CC, tid, 512);
            ld_tile_a(sbase, s2 + P1_B, B + (kc+1)*64, 128, CC, tid, 512);
            CP_COMMIT();
        }
        int st = (kc & 1) * STGP;
        mma_w16(c, sbase+st+P1_A, sbase+st+P1_B, wm0, wn0, lane);
    }
    const int gid = lane >> 2, tg = lane & 3;
    if (!isw){
        h16* Oh = zid ? g_Kh : g_Qh;
#pragma unroll
        for (int ma = 0; ma < 2; ma++)
#pragma unroll
        for (int na = 0; na < 4; na++){
            int col = n0 + wn0 + na*8 + tg*2;
            int h = col >> 6, z = col & 63;
#pragma unroll
            for (int half = 0; half < 2; half++){
                int row = m0 + wm0 + ma*16 + gid + half*8;
                int b = row >> 10, tk = row & (NN-1);
                size_t adr = ((size_t)(b*HH + h)*NN + tk)*ZZ + z;
                *reinterpret_cast<uint32_t*>(Oh + adr)
                    = pack2h(c[ma][na][half*2], c[ma][na][half*2+1]);
            }
        }
    } else {
        h16* Oh = sel ? g_U2h : g_U1h;
#pragma unroll
        for (int ma = 0; ma < 2; ma++)
#pragma unroll
        for (int na = 0; na < 4; na++){
            int row = m0 + wm0 + ma*16 + gid;
            int col = n0 + wn0 + na*8 + tg*2;
            *reinterpret_cast<uint32_t*>(Oh + (size_t)row*CC + col)
                = pack2h(c[ma][na][0], c[ma][na][1]);
            *reinterpret_cast<uint32_t*>(Oh + (size_t)(row+8)*CC + col)
                = pack2h(c[ma][na][2], c[ma][na][3]);
        }
    }
}

// ============================ flash stats (512 thr, 16 warps) ===============
#define ST_QH 0
#define ST_KH0 16384
#define ST_KH1 32768
#define ST_MM 49152
#define ST_LL 51200
#define ST_BYTES 53248
__global__ __launch_bounds__(512) void k_statsf(){
    extern __shared__ char sm[];
    const int tid = threadIdx.x, wid = tid >> 5, lane = tid & 31;
    const uint32_t sbase = smem_u32(sm);
    const int bh = blockIdx.y, q0 = blockIdx.x*128;
    const int wq = (wid & 3)*32, wt = (wid >> 2)*32;
    const int gid = lane >> 2, tg = lane & 3;

    ld_tile_a(sbase, ST_QH,  g_Qh + ((size_t)bh*NN + q0)*ZZ, 128, ZZ, tid, 512);
    ld_tile_a(sbase, ST_KH0, g_Kh + (size_t)bh*NN*ZZ,        128, ZZ, tid, 512);
    CP_COMMIT();

    float rm[2][2], rl[2][2];
#pragma unroll
    for (int i = 0; i < 2; i++)
#pragma unroll
    for (int j = 0; j < 2; j++){ rm[i][j] = -1e30f; rl[i][j] = 0.0f; }

    for (int it = 0; it < 8; it++){
        CP_WAIT0();
        __syncthreads();
        if (it + 1 < 8){
            int kb = ((it+1) & 1) ? ST_KH1 : ST_KH0;
            ld_tile_a(sbase, kb, g_Kh + ((size_t)bh*NN + (it+1)*128)*ZZ, 128, ZZ, tid, 512);
            CP_COMMIT();
        }
        int kcur = (it & 1) ? ST_KH1 : ST_KH0;

        float s[2][4][4];
#pragma unroll
        for (int i = 0; i < 2; i++)
#pragma unroll
        for (int j = 0; j < 4; j++)
#pragma unroll
        for (int k = 0; k < 4; k++) s[i][j][k] = 0.0f;

        mma_w16(s, sbase+ST_QH, sbase+kcur, wq, wt, lane);

#pragma unroll
        for (int ma = 0; ma < 2; ma++)
#pragma unroll
        for (int half = 0; half < 2; half++){
            float cm = -1e30f;
#pragma unroll
            for (int na = 0; na < 4; na++)
                cm = fmaxf(cm, fmaxf(s[ma][na][half*2], s[ma][na][half*2+1]));
            cm *= SCALE;
            cm = fmaxf(cm, __shfl_xor_sync(0xffffffffu, cm, 1));
            cm = fmaxf(cm, __shfl_xor_sync(0xffffffffu, cm, 2));
            float nm = fmaxf(rm[ma][half], cm);
            float ls = 0.0f;
#pragma unroll
            for (int na = 0; na < 4; na++)
                ls += fexp(s[ma][na][half*2]*SCALE - nm) + fexp(s[ma][na][half*2+1]*SCALE - nm);
            ls += __shfl_xor_sync(0xffffffffu, ls, 1);
            ls += __shfl_xor_sync(0xffffffffu, ls, 2);
            float d = fmaxf(rm[ma][half] - nm, -60.0f);
            rl[ma][half] = rl[ma][half]*fexp(d) + ls;
            rm[ma][half] = nm;
        }
    }
    float* smm = reinterpret_cast<float*>(sm + ST_MM);   // [4][128]
    float* sml = reinterpret_cast<float*>(sm + ST_LL);
    __syncthreads();
    if (tg == 0){
#pragma unroll
        for (int ma = 0; ma < 2; ma++)
#pragma unroll
        for (int half = 0; half < 2; half++){
            int q = wq + ma*16 + gid + half*8;
            int wti = wid >> 2;
            smm[wti*128 + q] = rm[ma][half];
            sml[wti*128 + q] = rl[ma][half];
        }
    }
    __syncthreads();
    if (tid < 128){
        float m = smm[tid], l = sml[tid];
#pragma unroll
        for (int g2 = 1; g2 < 4; g2++){
            float m2 = smm[g2*128 + tid], l2 = sml[g2*128 + tid];
            float nm = fmaxf(m, m2);
            l = l*fexp(fmaxf(m - nm, -60.0f)) + l2*fexp(fmaxf(m2 - nm, -60.0f));
            m = nm;
        }
        g_m [bh*NN + q0 + tid] = m;
        g_il[bh*NN + q0 + tid] = 1.0f / l;
    }
}

// ============================ fused attention pass (512 threads) ============
#define AT_KTH 0
#define AT_QC0 16384
#define AT_KC0 24576
#define AT_QC1 32768
#define AT_KC1 40960
#define AT_PH  49152
#define AT_MS  65536
#define AT_IL  66048
#define AT_BYTES 66560
__global__ __launch_bounds__(512) void k_attn_f(){
    extern __shared__ char sm[];
    const int tid = threadIdx.x, wid = tid >> 5, lane = tid & 31;
    const uint32_t sbase = smem_u32(sm);
    const int bh = blockIdx.y, t0 = blockIdx.x*128;
    const int gid = lane >> 2, tg = lane & 3;
    const int lr = lane & 15, lh = lane >> 4;
    const int srow_off = (lane & 7) + ((lane & 16) ? 8 : 0);
    const int scol8 = ((lane >> 3) & 1) * 8;
    float* ms = reinterpret_cast<float*>(sm + AT_MS);
    float* il = reinterpret_cast<float*>(sm + AT_IL);

    const int wz = wid >> 3, wt2 = (wid & 7)*16;
    float c[8][4];
#pragma unroll
    for (int j = 0; j < 8; j++)
#pragma unroll
    for (int k = 0; k < 4; k++) c[j][k] = 0.0f;

    const int wq1 = (wid & 1)*32, wt1 = (wid >> 1)*16;

    ld_tile_a(sbase, AT_KTH, g_Kh + ((size_t)bh*NN + t0)*ZZ, 128, ZZ, tid, 512);
    ld_tile_a(sbase, AT_QC0, g_Qh + (size_t)bh*NN*ZZ, 64, ZZ, tid, 512);
    ld_tile_a(sbase, AT_KC0, g_Kh + (size_t)bh*NN*ZZ, 64, ZZ, tid, 512);
    if (tid < 64)       ms[tid]      = g_m [bh*NN + tid];
    else if (tid < 128) il[tid - 64] = g_il[bh*NN + tid - 64];
    CP_COMMIT();

    for (int j = 0; j < 16; j++){
        const int nb = j & 1;
        const int qcb = nb ? AT_QC1 : AT_QC0;
        const int kcb = nb ? AT_KC1 : AT_KC0;
        CP_WAIT0();
        __syncthreads();
        if (j + 1 < 16){
            int q2 = (j+1)*64, b2 = (j+1) & 1;
            ld_tile_a(sbase, b2 ? AT_QC1 : AT_QC0, g_Qh + ((size_t)bh*NN + q2)*ZZ, 64, ZZ, tid, 512);
            ld_tile_a(sbase, b2 ? AT_KC1 : AT_KC0, g_Kh + ((size_t)bh*NN + q2)*ZZ, 64, ZZ, tid, 512);
            if (tid < 64)       ms[b2*64 + tid]      = g_m [bh*NN + q2 + tid];
            else if (tid < 128) il[b2*64 + tid - 64] = g_il[bh*NN + q2 + tid - 64];
            CP_COMMIT();
        }

        // ---- phase 1: S chunk (1-term) -> P smem (hi fp16); warp 32q x 16t ----
        {
            float s1[2][2][4];
#pragma unroll
            for (int i = 0; i < 2; i++)
#pragma unroll
            for (int jj = 0; jj < 2; jj++)
#pragma unroll
            for (int k = 0; k < 4; k++) s1[i][jj][k] = 0.0f;
#pragma unroll
            for (int ks = 0; ks < 4; ks++){
                uint32_t ah[2][4];
#pragma unroll
                for (int ma = 0; ma < 2; ma++){
                    uint32_t off = SW((wq1 + ma*16 + lr)*128 + (ks*2 + lh)*16);
                    ldsm_x4(ah[ma][0], ah[ma][1], ah[ma][2], ah[ma][3], sbase + qcb + off);
                }
                uint32_t bh4[4];
                {
                    uint32_t off = SW((wt1 + lr)*128 + (ks*2 + lh)*16);
                    ldsm_x4(bh4[0], bh4[1], bh4[2], bh4[3], sbase + AT_KTH + off);
                }
#pragma unroll
                for (int ma = 0; ma < 2; ma++){
                    mma16816(s1[ma][0], ah[ma], bh4[0], bh4[2]);
                    mma16816(s1[ma][1], ah[ma], bh4[1], bh4[3]);
                }
            }
#pragma unroll
            for (int ma = 0; ma < 2; ma++)
#pragma unroll
            for (int na = 0; na < 2; na++)
#pragma unroll
            for (int half = 0; half < 2; half++){
                int qloc = wq1 + ma*16 + gid + half*8;
                float M = ms[nb*64 + qloc], I = il[nb*64 + qloc];
                int tloc = wt1 + na*8 + tg*2;
                float p0 = fexp(s1[ma][na][half*2]  *SCALE - M)*I;
                float p1 = fexp(s1[ma][na][half*2+1]*SCALE - M)*I;
                uint32_t off = (uint32_t)(tloc >> 6)*8192 + SW(qloc*128 + (tloc & 63)*2);
                *reinterpret_cast<uint32_t*>(sm + AT_PH + off) = pack2h(p0, p1);
            }
        }
        __syncthreads();

        // ---- phase 2: Ck/Cq += P^T [K|Q]; warp 16t x 64z ----
        {
            const int bsh = wz ? qcb : kcb;
#pragma unroll
            for (int ks = 0; ks < 4; ks++){
                int qk = ks*16;
                uint32_t ah[4];
                {
                    uint32_t off = (uint32_t)(wt2 >> 6)*8192
                                 + SW((qk + srow_off)*128 + ((wt2 & 63) + scol8)*2);
                    ldsm_x4_t(ah[0], ah[1], ah[2], ah[3], sbase + AT_PH + off);
                }
                uint32_t bh4[4][4];
#pragma unroll
                for (int zn = 0; zn < 4; zn++){
                    uint32_t off = SW((qk + srow_off)*128 + (zn*16 + scol8)*2);
                    ldsm_x4_t(bh4[zn][0], bh4[zn][1], bh4[zn][2], bh4[zn][3], sbase + bsh + off);
                }
#pragma unroll
                for (int zn = 0; zn < 4; zn++){
                    mma16816(c[zn*2],   ah, bh4[zn][0], bh4[zn][2]);
                    mma16816(c[zn*2+1], ah, bh4[zn][1], bh4[zn][3]);
                }
            }
        }
    }
    const int b = bh / HH, h = bh - b*HH;
    h16* Oh = wz ? g_Cqh : g_Ckh;
#pragma unroll
    for (int na = 0; na < 8; na++){
        int z = na*8 + tg*2;
#pragma unroll
        for (int half = 0; half < 2; half++){
            int t = t0 + wt2 + gid + half*8;
            size_t adr = ((size_t)b*NN + t)*CC + h*ZZ + z;
            *reinterpret_cast<uint32_t*>(Oh + adr)
                = pack2h(c[na][half*2], c[na][half*2+1]);
        }
    }
}

// ================= out = Ck U1^T + Cq U2^T + bp (512 thr, 16 warps) =========
__global__ __launch_bounds__(512) void k_gemm_out(const float* __restrict__ bp,
                                                  float* __restrict__ out){
    MMA_PRE16();
    const int m0 = blockIdx.x*128, n0 = blockIdx.y*128;
    ld_tile_a(sbase, P1_A, g_Ckh + (size_t)m0*CC, 128, CC, tid, 512);
    ld_tile_a(sbase, P1_B, g_U1h + (size_t)n0*CC, 128, CC, tid, 512);
    CP_COMMIT();
    for (int it = 0; it < 24; it++){
        CP_WAIT0();
        __syncthreads();
        if (it + 1 < 24){
            int i2 = it + 1;
            int pr = i2 & 1, kc = i2 >> 1;
            const h16* A = pr ? g_Cqh : g_Ckh;
            const h16* B = pr ? g_U2h : g_U1h;
            int s2 = (i2 & 1) * STGP;
            ld_tile_a(sbase, s2 + P1_A, A + (size_t)m0*CC + kc*64, 128, CC, tid, 512);
            ld_tile_a(sbase, s2 + P1_B, B + (size_t)n0*CC + kc*64, 128, CC, tid, 512);
            CP_COMMIT();
        }
        int st = (it & 1) * STGP;
        mma_w16(c, sbase+st+P1_A, sbase+st+P1_B, wm0, wn0, lane);
    }
    const int gid = lane >> 2, tg = lane & 3;
#pragma unroll
    for (int ma = 0; ma < 2; ma++)
#pragma unroll
    for (int na = 0; na < 4; na++){
        int row = m0 + wm0 + ma*16 + gid;
        int col = n0 + wn0 + na*8 + tg*2;
        float b0 = bp[col], b1 = bp[col+1];
        *reinterpret_cast<float2*>(out + (size_t)row*CC + col)
            = make_float2(c[ma][na][0] + b0, c[ma][na][1] + b1);
        *reinterpret_cast<float2*>(out + (size_t)(row+8)*CC + col)
            = make_float2(c[ma][na][2] + b0, c[ma][na][3] + b1);
    }
}

// ============================ host ==========================================
extern "C" void kernel_launch(void* const* d_in, const int* in_sizes, int n_in,
                              void* d_out, int out_size)
{
    (void)in_sizes; (void)n_in; (void)out_size;
    const float* x  = (const float*)d_in[0];
    const float* Wq = (const float*)d_in[1];
    const float* Wk = (const float*)d_in[2];
    const float* Wp = (const float*)d_in[3];
    const float* bp = (const float*)d_in[4];
    float* out = (float*)d_out;

    cudaFuncSetAttribute(k_gemm_fused, cudaFuncAttributeMaxDynamicSharedMemorySize, SMEMP);
    cudaFuncSetAttribute(k_gemm_out,   cudaFuncAttributeMaxDynamicSharedMemorySize, SMEMP);
    cudaFuncSetAttribute(k_statsf,     cudaFuncAttributeMaxDynamicSharedMemorySize, ST_BYTES);
    cudaFuncSetAttribute(k_attn_f,     cudaFuncAttributeMaxDynamicSharedMemorySize, AT_BYTES);

    k_conv_all<<<288, 256>>>(x, Wq, Wk, Wp);
    k_gemm_fused<<<dim3(64, 6, 3), 512, SMEMP>>>();
    k_statsf<<<dim3(8, BH), 512, ST_BYTES>>>();
    k_attn_f<<<dim3(8, BH), 512, AT_BYTES>>>();
    k_gemm_out<<<dim3(64, 6), 512, SMEMP>>>(bp, out);
}